// round 6
// baseline (speedup 1.0000x reference)
#include <cuda_runtime.h>
#include <cstdint>

// PolyLoss: N=4096 rows, V=128 circular shifts, last dim = 2 (packed f32x2).
// per_shift[n,s] = (1/V) sum_v |pred[n,(s+v)%V] - gt[n,v]|_1 ; loss = mean_n min_s
//
// One warp per row. Lane L: t=L&15 owns shifts 8t..8t+7, h=L>>4 owns v-half
// [64h,64h+64). Sliding 6-entry register window (ulonglong2 = 2 packed-f32x2
// positions) over even/odd-split smem (sA/sB). Per 4-v block: 128 ACC instrs
// vs only 4 LDS.128 + 4 renames -> ~9% overhead. Halves combined via
// shfl_xor(16), then warp-min. Fused final reduction via last-CTA ticket.

#define NROWS 4096
#define V 128
#define RPC 4
#define NCTA (NROWS / RPC)    // 1024
#define THREADS 128

__device__ float g_partial[NCTA];
__device__ int g_ctr;

__device__ __forceinline__ uint64_t fma2(uint64_t a, uint64_t b, uint64_t c) {
    uint64_t d;
    asm("fma.rn.f32x2 %0, %1, %2, %3;" : "=l"(d) : "l"(a), "l"(b), "l"(c));
    return d;
}

// acc += | p - g | (componentwise, packed): FFMA2 + 2xLOP3 + FFMA2
#define ACC(p2, g2, acc) do {                      \
    uint64_t _d = fma2((g2), NEG1, (p2));          \
    _d &= 0x7fffffff7fffffffULL;                   \
    (acc) = fma2(_d, ONE1, (acc));                 \
} while (0)

__global__ void __launch_bounds__(THREADS, 8) polyloss_kernel(
    const float* __restrict__ pred, const float* __restrict__ gt,
    float* __restrict__ out)
{
    // Entry e_k = (pos 2k, pos 2k+1), k=0..63 circular. Even entries in sA,
    // odd in sB, each duplicated (sX[j]=sX[j+32]) so window indices q+m+3<=64
    // never wrap. sA[64]=e_0, sB[64]=e_1 pad.
    __shared__ ulonglong2 sA[RPC][66];
    __shared__ ulonglong2 sB[RPC][66];
    __shared__ ulonglong2 sg[RPC][64];
    __shared__ float s_rowmin[RPC];
    __shared__ int s_is_last;
    __shared__ float s_red[THREADS];

    const int tid  = threadIdx.x;
    const int w    = tid >> 5;
    const int lane = tid & 31;
    const int t    = lane & 15;     // shift group: shifts 8t..8t+7
    const int h    = lane >> 4;     // v-half
    const int row  = blockIdx.x * RPC + w;

    const uint64_t NEG1 = 0xBF800000BF800000ULL;
    const uint64_t ONE1 = 0x3F8000003F800000ULL;

    // ---- stage: each warp stages its own row (2 entries per lane + dups) ----
    {
        const ulonglong2* prow =
            reinterpret_cast<const ulonglong2*>(pred) + row * 64;
        const ulonglong2* grow =
            reinterpret_cast<const ulonglong2*>(gt)   + row * 64;
        ulonglong2 e1 = prow[lane];        // entry lane
        ulonglong2 e2 = prow[lane + 32];   // entry lane+32
        const int j = lane >> 1;
        if (lane & 1) {
            sB[w][j]      = e1; sB[w][j + 32] = e1;
            sB[w][j + 16] = e2; sB[w][j + 48] = e2;
        } else {
            sA[w][j]      = e1; sA[w][j + 32] = e1;
            sA[w][j + 16] = e2; sA[w][j + 48] = e2;
        }
        if (lane == 0) sA[w][64] = e1;     // pad = e_0
        if (lane == 1) sB[w][64] = e1;     // pad = e_1
        sg[w][lane]      = grow[lane];
        sg[w][lane + 32] = grow[lane + 32];
    }
    __syncwarp();

    // ---- mainloop: 16 blocks x 4 v's; window entries q+m .. q+m+2 in sA/sB
    //      (12 positions) covers shifts 8t..8t+7 x v-offsets 0..3 ----
    uint64_t a0 = 0, a1 = 0, a2 = 0, a3 = 0, a4 = 0, a5 = 0, a6 = 0, a7 = 0;
    const int q = 2 * t + 16 * h;
    const ulonglong2* Ap = sA[w];
    const ulonglong2* Bp = sB[w];
    const ulonglong2* gp = sg[w] + 32 * h;

    ulonglong2 Pa = Ap[q];      // positions 0,1   (rel. 2*(q+ m-part))
    ulonglong2 Pb = Bp[q];      // positions 2,3
    ulonglong2 Pc = Ap[q + 1];  // positions 4,5
    ulonglong2 Pd = Bp[q + 1];  // positions 6,7
    ulonglong2 Pe = Ap[q + 2];  // positions 8,9
    ulonglong2 Pf = Bp[q + 2];  // positions 10,11

    #pragma unroll
    for (int m = 0; m < 16; m++) {
        ulonglong2 G0 = gp[2 * m];       // gt[v0], gt[v0+1]
        ulonglong2 G1 = gp[2 * m + 1];   // gt[v0+2], gt[v0+3]
        // u=0: window positions r+0, r=0..7
        ACC(Pa.x, G0.x, a0); ACC(Pa.y, G0.x, a1); ACC(Pb.x, G0.x, a2); ACC(Pb.y, G0.x, a3);
        ACC(Pc.x, G0.x, a4); ACC(Pc.y, G0.x, a5); ACC(Pd.x, G0.x, a6); ACC(Pd.y, G0.x, a7);
        // u=1: positions r+1
        ACC(Pa.y, G0.y, a0); ACC(Pb.x, G0.y, a1); ACC(Pb.y, G0.y, a2); ACC(Pc.x, G0.y, a3);
        ACC(Pc.y, G0.y, a4); ACC(Pd.x, G0.y, a5); ACC(Pd.y, G0.y, a6); ACC(Pe.x, G0.y, a7);
        // u=2: positions r+2
        ACC(Pb.x, G1.x, a0); ACC(Pb.y, G1.x, a1); ACC(Pc.x, G1.x, a2); ACC(Pc.y, G1.x, a3);
        ACC(Pd.x, G1.x, a4); ACC(Pd.y, G1.x, a5); ACC(Pe.x, G1.x, a6); ACC(Pe.y, G1.x, a7);
        // u=3: positions r+3
        ACC(Pb.y, G1.y, a0); ACC(Pc.x, G1.y, a1); ACC(Pc.y, G1.y, a2); ACC(Pd.x, G1.y, a3);
        ACC(Pd.y, G1.y, a4); ACC(Pe.x, G1.y, a5); ACC(Pe.y, G1.y, a6); ACC(Pf.x, G1.y, a7);
        // slide by 1 index (2 entries = 4 positions); straight-line renames
        Pa = Pc; Pb = Pd; Pc = Pe; Pd = Pf;
        Pe = Ap[q + m + 3];
        Pf = Bp[q + m + 3];
    }

    // ---- per-shift partials: fold packed halves, combine v-halves, min ----
    float s0 = __uint_as_float((uint32_t)a0) + __uint_as_float((uint32_t)(a0 >> 32));
    float s1 = __uint_as_float((uint32_t)a1) + __uint_as_float((uint32_t)(a1 >> 32));
    float s2 = __uint_as_float((uint32_t)a2) + __uint_as_float((uint32_t)(a2 >> 32));
    float s3 = __uint_as_float((uint32_t)a3) + __uint_as_float((uint32_t)(a3 >> 32));
    float s4 = __uint_as_float((uint32_t)a4) + __uint_as_float((uint32_t)(a4 >> 32));
    float s5 = __uint_as_float((uint32_t)a5) + __uint_as_float((uint32_t)(a5 >> 32));
    float s6 = __uint_as_float((uint32_t)a6) + __uint_as_float((uint32_t)(a6 >> 32));
    float s7 = __uint_as_float((uint32_t)a7) + __uint_as_float((uint32_t)(a7 >> 32));
    // add the other v-half (lane t <-> lane t+16 hold same shifts)
    s0 += __shfl_xor_sync(0xffffffffu, s0, 16);
    s1 += __shfl_xor_sync(0xffffffffu, s1, 16);
    s2 += __shfl_xor_sync(0xffffffffu, s2, 16);
    s3 += __shfl_xor_sync(0xffffffffu, s3, 16);
    s4 += __shfl_xor_sync(0xffffffffu, s4, 16);
    s5 += __shfl_xor_sync(0xffffffffu, s5, 16);
    s6 += __shfl_xor_sync(0xffffffffu, s6, 16);
    s7 += __shfl_xor_sync(0xffffffffu, s7, 16);
    float mn = fminf(fminf(fminf(s0, s1), fminf(s2, s3)),
                     fminf(fminf(s4, s5), fminf(s6, s7)));
    #pragma unroll
    for (int off = 8; off > 0; off >>= 1)
        mn = fminf(mn, __shfl_xor_sync(0xffffffffu, mn, off));
    if (lane == 0) s_rowmin[w] = mn;
    __syncthreads();

    // ---- CTA partial + last-CTA ticket reduction ----
    if (tid == 0) {
        g_partial[blockIdx.x] =
            (s_rowmin[0] + s_rowmin[1]) + (s_rowmin[2] + s_rowmin[3]);
        __threadfence();
        int ticket = atomicAdd(&g_ctr, 1);
        s_is_last = (ticket == NCTA - 1);
    }
    __syncthreads();

    if (s_is_last) {
        __threadfence();
        float acc = 0.f;
        #pragma unroll
        for (int i = tid; i < NCTA; i += THREADS)
            acc += g_partial[i];
        s_red[tid] = acc;
        __syncthreads();
        #pragma unroll
        for (int off = THREADS / 2; off > 0; off >>= 1) {
            if (tid < off) s_red[tid] += s_red[tid + off];
            __syncthreads();
        }
        if (tid == 0) {
            out[0] = s_red[0] * (1.0f / ((float)NROWS * (float)V));
            g_ctr = 0;  // reset for next graph replay
        }
    }
}

extern "C" void kernel_launch(void* const* d_in, const int* in_sizes, int n_in,
                              void* d_out, int out_size)
{
    const float* pred = (const float*)d_in[0];
    const float* gt   = (const float*)d_in[1];
    polyloss_kernel<<<NCTA, THREADS>>>(pred, gt, (float*)d_out);
}